// round 8
// baseline (speedup 1.0000x reference)
#include <cuda_runtime.h>
#include <cstdint>

#define DINLINE __device__ __forceinline__

// ---------------------------------------------------------------------------
// Problem constants
// ---------------------------------------------------------------------------
constexpr int BATCH = 8192;
constexpr int HID   = 1024;
constexpr int KDIM  = 2048;               // I + H
constexpr int NTOT  = 4096;               // 4 gates * HID

constexpr int BM  = 128;                  // CTA M tile
constexpr int BN  = 128;                  // CTA N tile (4 gates x 32 h-cols)
constexpr int BNH = 32;                   // h-columns per CTA
constexpr int KC  = 32;                   // K per chunk (32 tf32 = 128 B/row)
constexpr int KI  = KDIM / KC;            // 64 chunks

constexpr int NSTAGE      = 3;
constexpr int STAGE_A     = BM * 128;     // 16 KB
constexpr int STAGE_B     = BN * 128;     // 16 KB
constexpr int STAGE_BYTES = STAGE_A + STAGE_B;            // 32 KB
constexpr int DYN_SMEM    = 1024 + NSTAGE * STAGE_BYTES;  // ~97 KB -> 2 CTAs/SM

// Scratch (allocation-free rule: __device__ globals)
__device__ float g_A[(size_t)BATCH * KDIM];   // 64 MB: tf32-rounded [x|h] (L2-hot)
__device__ float g_B[(size_t)NTOT * KDIM];    // 32 MB: tf32-rounded W^T (L2-resident)

// ---------------------------------------------------------------------------
// PTX helpers (base PTX only: cp.async / ldmatrix / mma.sync)
// ---------------------------------------------------------------------------
DINLINE uint32_t smem_u32(const void* p) {
    uint32_t a;
    asm("{ .reg .u64 t; cvta.to.shared.u64 t, %1; cvt.u32.u64 %0, t; }"
        : "=r"(a) : "l"(p));
    return a;
}

DINLINE void cp16(uint32_t dst, const void* src) {
    asm volatile("cp.async.cg.shared.global [%0], [%1], 16;"
                 :: "r"(dst), "l"(src) : "memory");
}
DINLINE void cp_commit() { asm volatile("cp.async.commit_group;" ::: "memory"); }
template <int N> DINLINE void cp_wait() {
    asm volatile("cp.async.wait_group %0;" :: "n"(N) : "memory");
}

// ldmatrix.x4 on tf32 data: one 8x8 b16 matrix == 8x4 f32 tile; lane l gets
// f32 element (row=l/4, col=l%4) -- exactly one tf32 mma fragment register.
DINLINE void ldsm4(uint32_t* r, uint32_t addr) {
    asm volatile("ldmatrix.sync.aligned.m8n8.x4.shared.b16 {%0,%1,%2,%3}, [%4];"
                 : "=r"(r[0]), "=r"(r[1]), "=r"(r[2]), "=r"(r[3]) : "r"(addr));
}

DINLINE void mma_tf32(float* d, const uint32_t* a, const uint32_t* b) {
    asm("mma.sync.aligned.m16n8k8.row.col.f32.tf32.tf32.f32 "
        "{%0,%1,%2,%3}, {%4,%5,%6,%7}, {%8,%9}, {%0,%1,%2,%3};"
        : "+f"(d[0]), "+f"(d[1]), "+f"(d[2]), "+f"(d[3])
        : "r"(a[0]), "r"(a[1]), "r"(a[2]), "r"(a[3]), "r"(b[0]), "r"(b[1]));
}

DINLINE float rtf(float x) {  // round-to-nearest tf32 (kills truncation bias)
    float y; asm("cvt.rna.tf32.f32 %0, %1;" : "=f"(y) : "f"(x)); return y;
}

DINLINE uint32_t SWZ(uint32_t b) { return b ^ ((b >> 3) & 0x70); }

DINLINE float sigm(float x)  { return __fdividef(1.0f, 1.0f + __expf(-x)); }
DINLINE float tanhe(float x) { return 1.0f - __fdividef(2.0f, __expf(2.0f * x) + 1.0f); }

// ---------------------------------------------------------------------------
// Prep kernels: tf32-round + pack A=[x|h], B=W^T (K-major)
// ---------------------------------------------------------------------------
__global__ void pack_a_kernel(const float* __restrict__ x,
                              const float* __restrict__ h) {
    size_t v = (size_t)blockIdx.x * blockDim.x + threadIdx.x;  // float4 index
    int m = (int)(v >> 9);            // 512 float4 per 2048-wide row
    int q = (int)(v & 511);
    const float* src = (q < 256) ? (x + (size_t)m * HID + (size_t)q * 4)
                                 : (h + (size_t)m * HID + (size_t)(q - 256) * 4);
    float4 val = *(const float4*)src;
    val.x = rtf(val.x); val.y = rtf(val.y); val.z = rtf(val.z); val.w = rtf(val.w);
    ((float4*)g_A)[v] = val;
}

__global__ void pack_b_kernel(const float* __restrict__ Wx,
                              const float* __restrict__ Wh) {
    __shared__ float tile[32][33];
    int k0 = blockIdx.x * 32;
    int n0 = blockIdx.y * 32;
    int tx = threadIdx.x, ty = threadIdx.y;  // (32, 8)
#pragma unroll
    for (int i = 0; i < 32; i += 8) {
        int k = k0 + ty + i;
        float v = (k < 1024) ? Wx[(size_t)k * NTOT + n0 + tx]
                             : Wh[(size_t)(k - 1024) * NTOT + n0 + tx];
        tile[ty + i][tx] = rtf(v);
    }
    __syncthreads();
#pragma unroll
    for (int i = 0; i < 32; i += 8) {
        int n = n0 + ty + i;
        g_B[(size_t)n * KDIM + k0 + tx] = tile[tx][ty + i];
    }
}

// ---------------------------------------------------------------------------
// Fused GEMM + LSTM epilogue (cp.async + ldmatrix + mma.sync.tf32)
// ---------------------------------------------------------------------------
// Grid = (nh fastest, m slowest): co-resident CTAs (adjacent bids) share the
// SAME m0 -> their A-tile reads fully overlap in L2.
//
// B smem row r (0..127) holds global N row:
//   n(r) = ((r>>4)&3)*1024 + nh0 + (r&15) + ((r>>6)&1)*16
// so each warp's 64 columns = {i,f,g,o} x 16 h-cols and each THREAD holds all
// four gate values for its (m, hcol) pairs -> register-only LSTM epilogue.
DINLINE void load_stage(uint32_t sbase, int s, int kc, int m0, int nh0, int tid) {
    const uint32_t sA = sbase + (uint32_t)s * STAGE_BYTES;
    const uint32_t sB = sA + STAGE_A;
    const float* gA = g_A + (size_t)m0 * KDIM + (size_t)kc * KC;
    const float* gB = g_B + (size_t)kc * KC;
#pragma unroll
    for (int i = 0; i < 8; i++) {          // A: 128 rows x 128B
        int ch = tid + (i << 7);
        int r = ch >> 3, kb = ch & 7;
        uint32_t off = (uint32_t)(r * 128 + kb * 16);
        cp16(sA + SWZ(off), (const char*)(gA + (size_t)r * KDIM) + kb * 16);
    }
#pragma unroll
    for (int i = 0; i < 8; i++) {          // B: 128 gate-interleaved N rows x 128B
        int ch = tid + (i << 7);
        int r = ch >> 3, kb = ch & 7;
        int n = ((r >> 4) & 3) * 1024 + nh0 + (r & 15) + ((r >> 6) & 1) * 16;
        uint32_t off = (uint32_t)(r * 128 + kb * 16);
        cp16(sB + SWZ(off), (const char*)(gB + (size_t)n * KDIM) + kb * 16);
    }
}

__global__ void __launch_bounds__(128, 2)
lstm_gemm_kernel(const float* __restrict__ c_in, const float* __restrict__ bx,
                 float* __restrict__ h_out, float* __restrict__ c_out) {
    extern __shared__ __align__(16) char dynsmem[];
    __shared__ float s_bias[BN];

    const int tid = threadIdx.x;
    const int wid = tid >> 5;
    const int lid = tid & 31;
    const int nh0 = blockIdx.x * BNH;   // nh fastest -> co-resident CTAs share m0
    const int m0  = blockIdx.y * BM;

    const int wm0 = (wid >> 1) * 64;   // warp M offset (2x2 warp grid, 64x64 tiles)
    const int wn0 = (wid & 1) * 64;    // warp N offset (smem B column space)

    uint32_t sbase = (smem_u32(dynsmem) + 1023u) & ~1023u;

    // bias cache, ordered identically to B smem columns
    {
        int r = tid;
        int n = ((r >> 4) & 3) * 1024 + nh0 + (r & 15) + ((r >> 6) & 1) * 16;
        s_bias[r] = bx[n];
    }

    // per-lane ldmatrix base offsets + constant swizzle mask (row&7)<<4.
    // A fragment {a0..a3} = {A[g][t], A[g+8][t], A[g][t+4], A[g+8][t+4]}
    //   -> matrices ROWS-first.  B fragment {b0,b1} -> matrices COLS-first.
    const uint32_t lrowA = (uint32_t)(((lid >> 3) & 1) * 8 + (lid & 7));
    const uint32_t lcolA = (uint32_t)(((lid >> 4) & 1) * 16);
    const uint32_t lrowB = (uint32_t)(((lid >> 4) & 1) * 8 + (lid & 7));
    const uint32_t lcolB = (uint32_t)(((lid >> 3) & 1) * 16);
    const uint32_t xm    = (uint32_t)((lid & 7) << 4);
    const uint32_t aOff = (uint32_t)(wm0 + lrowA) * 128u + lcolA;           // A tile
    const uint32_t bOff = STAGE_A + (uint32_t)(wn0 + lrowB) * 128u + lcolB; // B tile

    float acc[4][8][4];
#pragma unroll
    for (int i = 0; i < 4; i++)
#pragma unroll
        for (int j = 0; j < 8; j++)
#pragma unroll
            for (int r = 0; r < 4; r++) acc[i][j][r] = 0.0f;

    // prologue: fill all 3 stages (chunks 0..2)
    load_stage(sbase, 0, 0, m0, nh0, tid); cp_commit();
    load_stage(sbase, 1, 1, m0, nh0, tid); cp_commit();
    load_stage(sbase, 2, 2, m0, nh0, tid); cp_commit();

    int s = 0;
    for (int k = 0; k < KI; k++) {
        cp_wait<2>();        // chunk k complete (k+1, k+2 may pend)
        __syncthreads();     // chunk-k stores visible to all warps

        const uint32_t stA = sbase + (uint32_t)s * STAGE_BYTES + aOff;
        const uint32_t stB = sbase + (uint32_t)s * STAGE_BYTES + bOff;
#pragma unroll
        for (int ks = 0; ks < 4; ks++) {
            uint32_t af[4][4], bf[4][4];
#pragma unroll
            for (int i = 0; i < 4; i++)
                ldsm4(af[i], (stA + (uint32_t)(i * 2048 + ks * 32)) ^ xm);
#pragma unroll
            for (int jp = 0; jp < 4; jp++)
                ldsm4(bf[jp], (stB + (uint32_t)(jp * 2048 + ks * 32)) ^ xm);
#pragma unroll
            for (int i = 0; i < 4; i++)
#pragma unroll
                for (int j = 0; j < 8; j++)
                    mma_tf32(acc[i][j], af[i], &bf[j >> 1][(j & 1) * 2]);
        }

        __syncthreads();     // all warps done reading stage s
        if (k + 3 < KI) load_stage(sbase, s, k + 3, m0, nh0, tid);
        cp_commit();
        s++; if (s == NSTAGE) s = 0;
    }

    // ------------------------------------------------------------------
    // Register-only LSTM epilogue.
    // acc[i][j][r]: row = m0+wm0+i*16 + lid/4 + (r>>1)*8
    //               smem col = wn0 + j*8 + 2*(lid&3) + (r&1)
    // smem col c -> gate=(c>>4)&3, hcol=((c>>6)&1)*16 + (c&15)
    // ------------------------------------------------------------------
    const int wHc = (wid & 1) * 16;
#pragma unroll
    for (int i = 0; i < 4; i++) {
#pragma unroll
        for (int rh = 0; rh < 2; rh++) {
            const int m = m0 + wm0 + i * 16 + (lid >> 2) + rh * 8;
            const float* crow = c_in + (size_t)m * HID + nh0;
            float* hrow  = h_out + (size_t)m * HID + nh0;
            float* corow = c_out + (size_t)m * HID + nh0;
#pragma unroll
            for (int hb = 0; hb < 2; hb++) {
#pragma unroll
                for (int cc = 0; cc < 2; cc++) {
                    const int hc   = wHc + hb * 8 + (lid & 3) * 2 + cc;
                    const int colb = wn0 + hb * 8 + (lid & 3) * 2 + cc; // gate 0 col
                    const int rr   = rh * 2 + cc;
                    float zi = acc[i][0 + hb][rr] + s_bias[colb];
                    float zf = acc[i][2 + hb][rr] + s_bias[colb + 16];
                    float zg = acc[i][4 + hb][rr] + s_bias[colb + 32];
                    float zo = acc[i][6 + hb][rr] + s_bias[colb + 48];
                    float iv = sigm(zi), fv = sigm(zf);
                    float gv = tanhe(zg), ov = sigm(zo);
                    float cn = fv * crow[hc] + iv * gv;
                    corow[hc] = cn;
                    hrow[hc]  = ov * tanhe(cn);
                }
            }
        }
    }
}

// ---------------------------------------------------------------------------
// Launcher
// ---------------------------------------------------------------------------
extern "C" void kernel_launch(void* const* d_in, const int* in_sizes, int n_in,
                              void* d_out, int out_size) {
    (void)in_sizes; (void)n_in; (void)out_size;
    const float* x  = (const float*)d_in[0];
    const float* h  = (const float*)d_in[1];
    const float* c  = (const float*)d_in[2];
    const float* Wx = (const float*)d_in[3];
    const float* bx = (const float*)d_in[4];
    const float* Wh = (const float*)d_in[5];
    float* out   = (float*)d_out;
    float* h_out = out;
    float* c_out = out + (size_t)BATCH * HID;

    cudaFuncSetAttribute(lstm_gemm_kernel,
                         cudaFuncAttributeMaxDynamicSharedMemorySize, DYN_SMEM);

    // Prep: tf32-round + pack A=[x|h], B=W^T (K-major)
    pack_a_kernel<<<(BATCH * KDIM / 4) / 256, 256>>>(x, h);
    pack_b_kernel<<<dim3(KDIM / 32, NTOT / 32), dim3(32, 8)>>>(Wx, Wh);

    // Fused GEMM + LSTM epilogue (nh0 fastest -> co-resident CTAs share A)
    lstm_gemm_kernel<<<dim3(HID / BNH, BATCH / BM), 128, DYN_SMEM>>>(
        c, bx, h_out, c_out);
}

// round 10
// speedup vs baseline: 1.0362x; 1.0362x over previous
#include <cuda_runtime.h>
#include <cstdint>

#define DINLINE __device__ __forceinline__

// ---------------------------------------------------------------------------
// Problem constants
// ---------------------------------------------------------------------------
constexpr int BATCH = 8192;
constexpr int HID   = 1024;
constexpr int KDIM  = 2048;               // I + H
constexpr int NTOT  = 4096;               // 4 gates * HID

constexpr int BM  = 128;                  // CTA M tile
constexpr int BN  = 128;                  // CTA N tile (4 gates x 32 h-cols)
constexpr int BNH = 32;                   // h-columns per CTA
constexpr int KC  = 32;                   // K per chunk (32 tf32 = 128 B/row)
constexpr int KI  = KDIM / KC;            // 64 chunks

constexpr int NSTAGE      = 3;
constexpr int STAGE_A     = BM * 128;     // 16 KB
constexpr int STAGE_B     = BN * 128;     // 16 KB
constexpr int STAGE_BYTES = STAGE_A + STAGE_B;            // 32 KB
constexpr int DYN_SMEM    = 1024 + NSTAGE * STAGE_BYTES;  // ~97 KB -> 2 CTAs/SM

// Scratch (allocation-free rule: __device__ globals)
__device__ float g_A[(size_t)BATCH * KDIM];   // 64 MB: tf32-rounded [x|h] (L2-hot)
__device__ float g_B[(size_t)NTOT * KDIM];    // 32 MB: tf32-rounded W^T (L2-resident)

// ---------------------------------------------------------------------------
// PTX helpers (base PTX only: cp.async / ldmatrix / mma.sync)
// ---------------------------------------------------------------------------
DINLINE uint32_t smem_u32(const void* p) {
    uint32_t a;
    asm("{ .reg .u64 t; cvta.to.shared.u64 t, %1; cvt.u32.u64 %0, t; }"
        : "=r"(a) : "l"(p));
    return a;
}

DINLINE void cp16(uint32_t dst, const void* src) {
    asm volatile("cp.async.cg.shared.global [%0], [%1], 16;"
                 :: "r"(dst), "l"(src) : "memory");
}
DINLINE void cp_commit() { asm volatile("cp.async.commit_group;" ::: "memory"); }
template <int N> DINLINE void cp_wait() {
    asm volatile("cp.async.wait_group %0;" :: "n"(N) : "memory");
}

DINLINE void l2_prefetch(const void* p) {
    asm volatile("prefetch.global.L2 [%0];" :: "l"(p));
}

// ldmatrix.x4 on tf32 data: one 8x8 b16 matrix == 8x4 f32 tile; lane l gets
// f32 element (row=l/4, col=l%4) -- exactly one tf32 mma fragment register.
DINLINE void ldsm4(uint32_t* r, uint32_t addr) {
    asm volatile("ldmatrix.sync.aligned.m8n8.x4.shared.b16 {%0,%1,%2,%3}, [%4];"
                 : "=r"(r[0]), "=r"(r[1]), "=r"(r[2]), "=r"(r[3]) : "r"(addr));
}

DINLINE void mma_tf32(float* d, const uint32_t* a, const uint32_t* b) {
    asm("mma.sync.aligned.m16n8k8.row.col.f32.tf32.tf32.f32 "
        "{%0,%1,%2,%3}, {%4,%5,%6,%7}, {%8,%9}, {%0,%1,%2,%3};"
        : "+f"(d[0]), "+f"(d[1]), "+f"(d[2]), "+f"(d[3])
        : "r"(a[0]), "r"(a[1]), "r"(a[2]), "r"(a[3]), "r"(b[0]), "r"(b[1]));
}

DINLINE float rtf(float x) {  // round-to-nearest tf32 (kills truncation bias)
    float y; asm("cvt.rna.tf32.f32 %0, %1;" : "=f"(y) : "f"(x)); return y;
}

DINLINE uint32_t SWZ(uint32_t b) { return b ^ ((b >> 3) & 0x70); }

DINLINE float sigm(float x)  { return __fdividef(1.0f, 1.0f + __expf(-x)); }
DINLINE float tanhe(float x) { return 1.0f - __fdividef(2.0f, __expf(2.0f * x) + 1.0f); }

// ---------------------------------------------------------------------------
// Prep kernels: tf32-round + pack A=[x|h], B=W^T (K-major)
// ---------------------------------------------------------------------------
__global__ void pack_a_kernel(const float* __restrict__ x,
                              const float* __restrict__ h) {
    size_t v = (size_t)blockIdx.x * blockDim.x + threadIdx.x;  // float4 index
    int m = (int)(v >> 9);            // 512 float4 per 2048-wide row
    int q = (int)(v & 511);
    const float* src = (q < 256) ? (x + (size_t)m * HID + (size_t)q * 4)
                                 : (h + (size_t)m * HID + (size_t)(q - 256) * 4);
    float4 val = *(const float4*)src;
    val.x = rtf(val.x); val.y = rtf(val.y); val.z = rtf(val.z); val.w = rtf(val.w);
    ((float4*)g_A)[v] = val;
}

__global__ void pack_b_kernel(const float* __restrict__ Wx,
                              const float* __restrict__ Wh) {
    __shared__ float tile[32][33];
    int k0 = blockIdx.x * 32;
    int n0 = blockIdx.y * 32;
    int tx = threadIdx.x, ty = threadIdx.y;  // (32, 8)
#pragma unroll
    for (int i = 0; i < 32; i += 8) {
        int k = k0 + ty + i;
        float v = (k < 1024) ? Wx[(size_t)k * NTOT + n0 + tx]
                             : Wh[(size_t)(k - 1024) * NTOT + n0 + tx];
        tile[ty + i][tx] = rtf(v);
    }
    __syncthreads();
#pragma unroll
    for (int i = 0; i < 32; i += 8) {
        int n = n0 + ty + i;
        g_B[(size_t)n * KDIM + k0 + tx] = tile[tx][ty + i];
    }
}

// ---------------------------------------------------------------------------
// Fused GEMM + LSTM epilogue (cp.async + ldmatrix + mma.sync.tf32)
// ---------------------------------------------------------------------------
// Grid = (m fastest, nh slowest): all 64 CTAs of one nh0 column reuse the SAME
// 1 MB B slice (64x L2 reuse) while A streams once.
//
// B smem row r (0..127) holds global N row:
//   n(r) = ((r>>4)&3)*1024 + nh0 + (r&15) + ((r>>6)&1)*16
// so each warp's 64 columns = {i,f,g,o} x 16 h-cols and each THREAD holds all
// four gate values for its (m, hcol) pairs -> register-only LSTM epilogue.
DINLINE void load_stage(uint32_t sbase, int s, int kc, int m0, int nh0, int tid) {
    const uint32_t sA = sbase + (uint32_t)s * STAGE_BYTES;
    const uint32_t sB = sA + STAGE_A;
    const float* gA = g_A + (size_t)m0 * KDIM + (size_t)kc * KC;
    const float* gB = g_B + (size_t)kc * KC;
#pragma unroll
    for (int i = 0; i < 8; i++) {          // A: 128 rows x 128B
        int ch = tid + (i << 7);
        int r = ch >> 3, kb = ch & 7;
        uint32_t off = (uint32_t)(r * 128 + kb * 16);
        cp16(sA + SWZ(off), (const char*)(gA + (size_t)r * KDIM) + kb * 16);
    }
#pragma unroll
    for (int i = 0; i < 8; i++) {          // B: 128 gate-interleaved N rows x 128B
        int ch = tid + (i << 7);
        int r = ch >> 3, kb = ch & 7;
        int n = ((r >> 4) & 3) * 1024 + nh0 + (r & 15) + ((r >> 6) & 1) * 16;
        uint32_t off = (uint32_t)(r * 128 + kb * 16);
        cp16(sB + SWZ(off), (const char*)(gB + (size_t)n * KDIM) + kb * 16);
    }
}

__global__ void __launch_bounds__(128, 2)
lstm_gemm_kernel(const float* __restrict__ c_in, const float* __restrict__ bx,
                 float* __restrict__ h_out, float* __restrict__ c_out) {
    extern __shared__ __align__(16) char dynsmem[];
    __shared__ float s_bias[BN];

    const int tid = threadIdx.x;
    const int wid = tid >> 5;
    const int lid = tid & 31;
    const int m0  = blockIdx.x * BM;    // m fastest (proven best)
    const int nh0 = blockIdx.y * BNH;

    const int wm0 = (wid >> 1) * 64;   // warp M offset (2x2 warp grid, 64x64 tiles)
    const int wn0 = (wid & 1) * 64;    // warp N offset (smem B column space)

    uint32_t sbase = (smem_u32(dynsmem) + 1023u) & ~1023u;

    // bias cache, ordered identically to B smem columns
    {
        int r = tid;
        int n = ((r >> 4) & 3) * 1024 + nh0 + (r & 15) + ((r >> 6) & 1) * 16;
        s_bias[r] = bx[n];
    }

    // Warm L2 for the epilogue's c_in tile (one 128B line per thread).
    l2_prefetch(c_in + (size_t)(m0 + tid) * HID + nh0);

    // per-lane ldmatrix base offsets + constant swizzle mask (row&7)<<4.
    // A fragment {a0..a3} = {A[g][t], A[g+8][t], A[g][t+4], A[g+8][t+4]}
    //   -> matrices ROWS-first.  B fragment {b0,b1} -> matrices COLS-first.
    const uint32_t lrowA = (uint32_t)(((lid >> 3) & 1) * 8 + (lid & 7));
    const uint32_t lcolA = (uint32_t)(((lid >> 4) & 1) * 16);
    const uint32_t lrowB = (uint32_t)(((lid >> 4) & 1) * 8 + (lid & 7));
    const uint32_t lcolB = (uint32_t)(((lid >> 3) & 1) * 16);
    const uint32_t xm    = (uint32_t)((lid & 7) << 4);
    const uint32_t aOff = (uint32_t)(wm0 + lrowA) * 128u + lcolA;           // A tile
    const uint32_t bOff = STAGE_A + (uint32_t)(wn0 + lrowB) * 128u + lcolB; // B tile

    float acc[4][8][4];
#pragma unroll
    for (int i = 0; i < 4; i++)
#pragma unroll
        for (int j = 0; j < 8; j++)
#pragma unroll
            for (int r = 0; r < 4; r++) acc[i][j][r] = 0.0f;

    // prologue: preload chunks 0,1 into stages 0,1 (2 committed groups)
    load_stage(sbase, 0, 0, m0, nh0, tid); cp_commit();
    load_stage(sbase, 1, 1, m0, nh0, tid); cp_commit();

    int s = 0;
    for (int k = 0; k < KI; k++) {
        // Pending groups here: {k, k+1} (the valid ones). wait<1> leaves at
        // most 1 pending -> chunk k is COMPLETE. [R9's wait<2> at this spot
        // allowed chunk k in-flight -> data race; group math fixed.]
        if (k + 1 < KI) cp_wait<1>(); else cp_wait<0>();
        // Single barrier: (a) chunk-k stores visible to all warps,
        // (b) all warps finished chunk k-1 -> stage (s+2)%3 reusable.
        __syncthreads();

        // Issue chunk k+2 BEFORE compute: max DMA lead over the ~1000-cyc body.
        if (k + 2 < KI) {
            int sl = s + 2; if (sl >= NSTAGE) sl -= NSTAGE;
            load_stage(sbase, sl, k + 2, m0, nh0, tid);
        }
        cp_commit();   // commit every iter (empty groups keep the count aligned)

        const uint32_t stA = sbase + (uint32_t)s * STAGE_BYTES + aOff;
        const uint32_t stB = sbase + (uint32_t)s * STAGE_BYTES + bOff;
#pragma unroll
        for (int ks = 0; ks < 4; ks++) {
            uint32_t af[4][4], bf[4][4];
#pragma unroll
            for (int i = 0; i < 4; i++)
                ldsm4(af[i], (stA + (uint32_t)(i * 2048 + ks * 32)) ^ xm);
#pragma unroll
            for (int jp = 0; jp < 4; jp++)
                ldsm4(bf[jp], (stB + (uint32_t)(jp * 2048 + ks * 32)) ^ xm);
#pragma unroll
            for (int i = 0; i < 4; i++)
#pragma unroll
                for (int j = 0; j < 8; j++)
                    mma_tf32(acc[i][j], af[i], &bf[j >> 1][(j & 1) * 2]);
        }

        s++; if (s == NSTAGE) s = 0;
    }

    // ------------------------------------------------------------------
    // Register-only LSTM epilogue.
    // acc[i][j][r]: row = m0+wm0+i*16 + lid/4 + (r>>1)*8
    //               smem col = wn0 + j*8 + 2*(lid&3) + (r&1)
    // smem col c -> gate=(c>>4)&3, hcol=((c>>6)&1)*16 + (c&15)
    // ------------------------------------------------------------------
    const int wHc = (wid & 1) * 16;
#pragma unroll
    for (int i = 0; i < 4; i++) {
#pragma unroll
        for (int rh = 0; rh < 2; rh++) {
            const int m = m0 + wm0 + i * 16 + (lid >> 2) + rh * 8;
            const float* crow = c_in + (size_t)m * HID + nh0;
            float* hrow  = h_out + (size_t)m * HID + nh0;
            float* corow = c_out + (size_t)m * HID + nh0;
#pragma unroll
            for (int hb = 0; hb < 2; hb++) {
#pragma unroll
                for (int cc = 0; cc < 2; cc++) {
                    const int hc   = wHc + hb * 8 + (lid & 3) * 2 + cc;
                    const int colb = wn0 + hb * 8 + (lid & 3) * 2 + cc; // gate 0 col
                    const int rr   = rh * 2 + cc;
                    float zi = acc[i][0 + hb][rr] + s_bias[colb];
                    float zf = acc[i][2 + hb][rr] + s_bias[colb + 16];
                    float zg = acc[i][4 + hb][rr] + s_bias[colb + 32];
                    float zo = acc[i][6 + hb][rr] + s_bias[colb + 48];
                    float iv = sigm(zi), fv = sigm(zf);
                    float gv = tanhe(zg), ov = sigm(zo);
                    float cn = fv * crow[hc] + iv * gv;
                    corow[hc] = cn;
                    hrow[hc]  = ov * tanhe(cn);
                }
            }
        }
    }
}

// ---------------------------------------------------------------------------
// Launcher
// ---------------------------------------------------------------------------
extern "C" void kernel_launch(void* const* d_in, const int* in_sizes, int n_in,
                              void* d_out, int out_size) {
    (void)in_sizes; (void)n_in; (void)out_size;
    const float* x  = (const float*)d_in[0];
    const float* h  = (const float*)d_in[1];
    const float* c  = (const float*)d_in[2];
    const float* Wx = (const float*)d_in[3];
    const float* bx = (const float*)d_in[4];
    const float* Wh = (const float*)d_in[5];
    float* out   = (float*)d_out;
    float* h_out = out;
    float* c_out = out + (size_t)BATCH * HID;

    cudaFuncSetAttribute(lstm_gemm_kernel,
                         cudaFuncAttributeMaxDynamicSharedMemorySize, DYN_SMEM);

    // Prep: tf32-round + pack A=[x|h], B=W^T (K-major)
    pack_a_kernel<<<(BATCH * KDIM / 4) / 256, 256>>>(x, h);
    pack_b_kernel<<<dim3(KDIM / 32, NTOT / 32), dim3(32, 8)>>>(Wx, Wh);

    // Fused GEMM + LSTM epilogue (m0 fastest -> co-resident CTAs share B slice)
    lstm_gemm_kernel<<<dim3(BATCH / BM, HID / BNH), 128, DYN_SMEM>>>(
        c, bx, h_out, c_out);
}

// round 11
// speedup vs baseline: 1.0433x; 1.0068x over previous
#include <cuda_runtime.h>
#include <cstdint>

#define DINLINE __device__ __forceinline__

// ---------------------------------------------------------------------------
// Problem constants
// ---------------------------------------------------------------------------
constexpr int BATCH = 8192;
constexpr int HID   = 1024;
constexpr int KDIM  = 2048;               // I + H
constexpr int NTOT  = 4096;               // 4 gates * HID

constexpr int BM  = 128;                  // CTA M tile
constexpr int BN  = 128;                  // CTA N tile (4 gates x 32 h-cols)
constexpr int BNH = 32;                   // h-columns per CTA
constexpr int KC  = 32;                   // K per chunk (32 tf32 = 128 B/row)
constexpr int KI  = KDIM / KC;            // 64 chunks

constexpr int NSTAGE      = 3;
constexpr int STAGE_A     = BM * 128;     // 16 KB
constexpr int STAGE_B     = BN * 128;     // 16 KB
constexpr int STAGE_BYTES = STAGE_A + STAGE_B;            // 32 KB
constexpr int DYN_SMEM    = 1024 + NSTAGE * STAGE_BYTES;  // ~97 KB -> 2 CTAs/SM

// Merged prep kernel block split
constexpr int PACKA_BLOCKS = (BATCH * KDIM / 4) / 256;    // 16384
constexpr int PACKB_BLOCKS = (KDIM / 32) * (NTOT / 32);   // 8192

// Scratch (allocation-free rule: __device__ globals)
__device__ float g_A[(size_t)BATCH * KDIM];   // 64 MB: tf32-rounded [x|h]
__device__ float g_B[(size_t)NTOT * KDIM];    // 32 MB: tf32-rounded W^T
// Both fit L2 (96 MB < 126 MB): GEMM runs ~all-L2 (measured DRAM ~9.6%).

// ---------------------------------------------------------------------------
// PTX helpers (base PTX only: cp.async / ldmatrix / mma.sync)
// ---------------------------------------------------------------------------
DINLINE uint32_t smem_u32(const void* p) {
    uint32_t a;
    asm("{ .reg .u64 t; cvta.to.shared.u64 t, %1; cvt.u32.u64 %0, t; }"
        : "=r"(a) : "l"(p));
    return a;
}

DINLINE void cp16(uint32_t dst, const void* src) {
    asm volatile("cp.async.cg.shared.global [%0], [%1], 16;"
                 :: "r"(dst), "l"(src) : "memory");
}
DINLINE void cp_commit() { asm volatile("cp.async.commit_group;" ::: "memory"); }
template <int N> DINLINE void cp_wait() {
    asm volatile("cp.async.wait_group %0;" :: "n"(N) : "memory");
}

DINLINE void l2_prefetch(const void* p) {
    asm volatile("prefetch.global.L2 [%0];" :: "l"(p));
}

// ldmatrix.x4 on tf32 data: one 8x8 b16 matrix == 8x4 f32 tile; lane l gets
// f32 element (row=l/4, col=l%4) -- exactly one tf32 mma fragment register.
DINLINE void ldsm4(uint32_t* r, uint32_t addr) {
    asm volatile("ldmatrix.sync.aligned.m8n8.x4.shared.b16 {%0,%1,%2,%3}, [%4];"
                 : "=r"(r[0]), "=r"(r[1]), "=r"(r[2]), "=r"(r[3]) : "r"(addr));
}

DINLINE void mma_tf32(float* d, const uint32_t* a, const uint32_t* b) {
    asm("mma.sync.aligned.m16n8k8.row.col.f32.tf32.tf32.f32 "
        "{%0,%1,%2,%3}, {%4,%5,%6,%7}, {%8,%9}, {%0,%1,%2,%3};"
        : "+f"(d[0]), "+f"(d[1]), "+f"(d[2]), "+f"(d[3])
        : "r"(a[0]), "r"(a[1]), "r"(a[2]), "r"(a[3]), "r"(b[0]), "r"(b[1]));
}

DINLINE float rtf(float x) {  // round-to-nearest tf32 (kills truncation bias)
    float y; asm("cvt.rna.tf32.f32 %0, %1;" : "=f"(y) : "f"(x)); return y;
}

DINLINE uint32_t SWZ(uint32_t b) { return b ^ ((b >> 3) & 0x70); }

DINLINE float sigm(float x)  { return __fdividef(1.0f, 1.0f + __expf(-x)); }
DINLINE float tanhe(float x) { return 1.0f - __fdividef(2.0f, __expf(2.0f * x) + 1.0f); }

// ---------------------------------------------------------------------------
// Merged prep kernel: blocks [0, PACKA_BLOCKS) pack A=[x|h]; the rest pack
// B=W^T (K-major). One DRAM-bound launch instead of two sequential ones.
// ---------------------------------------------------------------------------
__global__ void pack_ab_kernel(const float* __restrict__ x,
                               const float* __restrict__ h,
                               const float* __restrict__ Wx,
                               const float* __restrict__ Wh) {
    const int tid = threadIdx.x;            // 256 threads
    if (blockIdx.x < PACKA_BLOCKS) {
        // ---- pack A: tf32-round + concat [x|h] ----
        size_t v = (size_t)blockIdx.x * 256 + tid;   // float4 index
        int m = (int)(v >> 9);              // 512 float4 per 2048-wide row
        int q = (int)(v & 511);
        const float* src = (q < 256) ? (x + (size_t)m * HID + (size_t)q * 4)
                                     : (h + (size_t)m * HID + (size_t)(q - 256) * 4);
        float4 val = *(const float4*)src;
        val.x = rtf(val.x); val.y = rtf(val.y);
        val.z = rtf(val.z); val.w = rtf(val.w);
        ((float4*)g_A)[v] = val;
    } else {
        // ---- pack B: tf32-round + transpose W -> [N, K] ----
        __shared__ float tile[32][33];
        int bb = blockIdx.x - PACKA_BLOCKS;
        int k0 = (bb & 63) * 32;            // 64 k-blocks
        int n0 = (bb >> 6) * 32;            // 128 n-blocks
        int tx = tid & 31, ty = tid >> 5;   // (32, 8)
#pragma unroll
        for (int i = 0; i < 32; i += 8) {
            int k = k0 + ty + i;
            float v = (k < 1024) ? Wx[(size_t)k * NTOT + n0 + tx]
                                 : Wh[(size_t)(k - 1024) * NTOT + n0 + tx];
            tile[ty + i][tx] = rtf(v);
        }
        __syncthreads();
#pragma unroll
        for (int i = 0; i < 32; i += 8) {
            int n = n0 + ty + i;
            g_B[(size_t)n * KDIM + k0 + tx] = tile[tx][ty + i];
        }
    }
}

// ---------------------------------------------------------------------------
// Fused GEMM + LSTM epilogue (cp.async + ldmatrix + mma.sync.tf32)
// R4 mainloop restored verbatim: wait<2> -> sync -> compute -> sync -> refill
// consumed stage. Every structural variant tried (deeper ring, single barrier,
// load-first, grid swap, L2 hints) measured equal or slower.
// ---------------------------------------------------------------------------
// Grid = (m fastest, nh slowest): all 64 CTAs of one nh0 column reuse the SAME
// 1 MB B slice in L2 while A streams once.
//
// B smem row r (0..127) holds global N row:
//   n(r) = ((r>>4)&3)*1024 + nh0 + (r&15) + ((r>>6)&1)*16
// so each warp's 64 columns = {i,f,g,o} x 16 h-cols and each THREAD holds all
// four gate values for its (m, hcol) pairs -> register-only LSTM epilogue.
DINLINE void load_stage(uint32_t sbase, int s, int kc, int m0, int nh0, int tid) {
    const uint32_t sA = sbase + (uint32_t)s * STAGE_BYTES;
    const uint32_t sB = sA + STAGE_A;
    const float* gA = g_A + (size_t)m0 * KDIM + (size_t)kc * KC;
    const float* gB = g_B + (size_t)kc * KC;
#pragma unroll
    for (int i = 0; i < 8; i++) {          // A: 128 rows x 128B
        int ch = tid + (i << 7);
        int r = ch >> 3, kb = ch & 7;
        uint32_t off = (uint32_t)(r * 128 + kb * 16);
        cp16(sA + SWZ(off), (const char*)(gA + (size_t)r * KDIM) + kb * 16);
    }
#pragma unroll
    for (int i = 0; i < 8; i++) {          // B: 128 gate-interleaved N rows x 128B
        int ch = tid + (i << 7);
        int r = ch >> 3, kb = ch & 7;
        int n = ((r >> 4) & 3) * 1024 + nh0 + (r & 15) + ((r >> 6) & 1) * 16;
        uint32_t off = (uint32_t)(r * 128 + kb * 16);
        cp16(sB + SWZ(off), (const char*)(gB + (size_t)n * KDIM) + kb * 16);
    }
}

__global__ void __launch_bounds__(128, 2)
lstm_gemm_kernel(const float* __restrict__ c_in, const float* __restrict__ bx,
                 float* __restrict__ h_out, float* __restrict__ c_out) {
    extern __shared__ __align__(16) char dynsmem[];
    __shared__ float s_bias[BN];

    const int tid = threadIdx.x;
    const int wid = tid >> 5;
    const int lid = tid & 31;
    const int m0  = blockIdx.x * BM;    // m fastest (proven best)
    const int nh0 = blockIdx.y * BNH;

    const int wm0 = (wid >> 1) * 64;   // warp M offset (2x2 warp grid, 64x64 tiles)
    const int wn0 = (wid & 1) * 64;    // warp N offset (smem B column space)

    uint32_t sbase = (smem_u32(dynsmem) + 1023u) & ~1023u;

    // bias cache, ordered identically to B smem columns
    {
        int r = tid;
        int n = ((r >> 4) & 3) * 1024 + nh0 + (r & 15) + ((r >> 6) & 1) * 16;
        s_bias[r] = bx[n];
    }

    // Warm L2 for the epilogue's c_in tile (one 128B line per thread).
    l2_prefetch(c_in + (size_t)(m0 + tid) * HID + nh0);

    // per-lane ldmatrix base offsets + constant swizzle mask (row&7)<<4.
    // A fragment {a0..a3} = {A[g][t], A[g+8][t], A[g][t+4], A[g+8][t+4]}
    //   -> matrices ROWS-first.  B fragment {b0,b1} -> matrices COLS-first.
    const uint32_t lrowA = (uint32_t)(((lid >> 3) & 1) * 8 + (lid & 7));
    const uint32_t lcolA = (uint32_t)(((lid >> 4) & 1) * 16);
    const uint32_t lrowB = (uint32_t)(((lid >> 4) & 1) * 8 + (lid & 7));
    const uint32_t lcolB = (uint32_t)(((lid >> 3) & 1) * 16);
    const uint32_t xm    = (uint32_t)((lid & 7) << 4);
    const uint32_t aOff = (uint32_t)(wm0 + lrowA) * 128u + lcolA;           // A tile
    const uint32_t bOff = STAGE_A + (uint32_t)(wn0 + lrowB) * 128u + lcolB; // B tile

    float acc[4][8][4];
#pragma unroll
    for (int i = 0; i < 4; i++)
#pragma unroll
        for (int j = 0; j < 8; j++)
#pragma unroll
            for (int r = 0; r < 4; r++) acc[i][j][r] = 0.0f;

    // prologue: fill all 3 stages (chunks 0..2)
    load_stage(sbase, 0, 0, m0, nh0, tid); cp_commit();
    load_stage(sbase, 1, 1, m0, nh0, tid); cp_commit();
    load_stage(sbase, 2, 2, m0, nh0, tid); cp_commit();

    int s = 0;
    for (int k = 0; k < KI; k++) {
        cp_wait<2>();        // chunk k complete (k+1, k+2 may pend)
        __syncthreads();     // chunk-k stores visible to all warps

        const uint32_t stA = sbase + (uint32_t)s * STAGE_BYTES + aOff;
        const uint32_t stB = sbase + (uint32_t)s * STAGE_BYTES + bOff;
#pragma unroll
        for (int ks = 0; ks < 4; ks++) {
            uint32_t af[4][4], bf[4][4];
#pragma unroll
            for (int i = 0; i < 4; i++)
                ldsm4(af[i], (stA + (uint32_t)(i * 2048 + ks * 32)) ^ xm);
#pragma unroll
            for (int jp = 0; jp < 4; jp++)
                ldsm4(bf[jp], (stB + (uint32_t)(jp * 2048 + ks * 32)) ^ xm);
#pragma unroll
            for (int i = 0; i < 4; i++)
#pragma unroll
                for (int j = 0; j < 8; j++)
                    mma_tf32(acc[i][j], af[i], &bf[j >> 1][(j & 1) * 2]);
        }

        __syncthreads();     // all warps done reading stage s
        if (k + 3 < KI) load_stage(sbase, s, k + 3, m0, nh0, tid);
        cp_commit();
        s++; if (s == NSTAGE) s = 0;
    }

    // ------------------------------------------------------------------
    // Register-only LSTM epilogue.
    // acc[i][j][r]: row = m0+wm0+i*16 + lid/4 + (r>>1)*8
    //               smem col = wn0 + j*8 + 2*(lid&3) + (r&1)
    // smem col c -> gate=(c>>4)&3, hcol=((c>>6)&1)*16 + (c&15)
    // ------------------------------------------------------------------
    const int wHc = (wid & 1) * 16;
#pragma unroll
    for (int i = 0; i < 4; i++) {
#pragma unroll
        for (int rh = 0; rh < 2; rh++) {
            const int m = m0 + wm0 + i * 16 + (lid >> 2) + rh * 8;
            const float* crow = c_in + (size_t)m * HID + nh0;
            float* hrow  = h_out + (size_t)m * HID + nh0;
            float* corow = c_out + (size_t)m * HID + nh0;
#pragma unroll
            for (int hb = 0; hb < 2; hb++) {
#pragma unroll
                for (int cc = 0; cc < 2; cc++) {
                    const int hc   = wHc + hb * 8 + (lid & 3) * 2 + cc;
                    const int colb = wn0 + hb * 8 + (lid & 3) * 2 + cc; // gate 0 col
                    const int rr   = rh * 2 + cc;
                    float zi = acc[i][0 + hb][rr] + s_bias[colb];
                    float zf = acc[i][2 + hb][rr] + s_bias[colb + 16];
                    float zg = acc[i][4 + hb][rr] + s_bias[colb + 32];
                    float zo = acc[i][6 + hb][rr] + s_bias[colb + 48];
                    float iv = sigm(zi), fv = sigm(zf);
                    float gv = tanhe(zg), ov = sigm(zo);
                    float cn = fv * crow[hc] + iv * gv;
                    corow[hc] = cn;
                    hrow[hc]  = ov * tanhe(cn);
                }
            }
        }
    }
}

// ---------------------------------------------------------------------------
// Launcher
// ---------------------------------------------------------------------------
extern "C" void kernel_launch(void* const* d_in, const int* in_sizes, int n_in,
                              void* d_out, int out_size) {
    (void)in_sizes; (void)n_in; (void)out_size;
    const float* x  = (const float*)d_in[0];
    const float* h  = (const float*)d_in[1];
    const float* c  = (const float*)d_in[2];
    const float* Wx = (const float*)d_in[3];
    const float* bx = (const float*)d_in[4];
    const float* Wh = (const float*)d_in[5];
    float* out   = (float*)d_out;
    float* h_out = out;
    float* c_out = out + (size_t)BATCH * HID;

    cudaFuncSetAttribute(lstm_gemm_kernel,
                         cudaFuncAttributeMaxDynamicSharedMemorySize, DYN_SMEM);

    // Merged prep: tf32-round + pack A=[x|h] and B=W^T in ONE launch
    pack_ab_kernel<<<PACKA_BLOCKS + PACKB_BLOCKS, 256>>>(x, h, Wx, Wh);

    // Fused GEMM + LSTM epilogue (m0 fastest -> co-resident CTAs share B slice)
    lstm_gemm_kernel<<<dim3(BATCH / BM, HID / BNH), 128, DYN_SMEM>>>(
        c, bx, h_out, c_out);
}

// round 12
// speedup vs baseline: 1.8801x; 1.8022x over previous
#include <cuda_runtime.h>
#include <cuda_fp16.h>
#include <cstdint>

#define DINLINE __device__ __forceinline__

// ---------------------------------------------------------------------------
// Problem constants
// ---------------------------------------------------------------------------
constexpr int BATCH = 8192;
constexpr int HID   = 1024;
constexpr int KDIM  = 2048;               // I + H
constexpr int NTOT  = 4096;               // 4 gates * HID

constexpr int BM  = 128;                  // CTA M tile
constexpr int BN  = 128;                  // CTA N tile (4 gates x 32 h-cols)
constexpr int BNH = 32;                   // h-columns per CTA
constexpr int KC  = 64;                   // K per chunk (64 fp16 = 128 B/row)
constexpr int KI  = KDIM / KC;            // 32 chunks

constexpr int NSTAGE      = 3;
constexpr int STAGE_A     = BM * 128;     // 16 KB
constexpr int STAGE_B     = BN * 128;     // 16 KB
constexpr int STAGE_BYTES = STAGE_A + STAGE_B;            // 32 KB
constexpr int DYN_SMEM    = 1024 + NSTAGE * STAGE_BYTES;  // ~97 KB -> 2 CTAs/SM

// Merged prep kernel block split
constexpr int PACKA_BLOCKS = (BATCH * KDIM / 8) / 256;    // 8192 (8 halves/thr)
constexpr int PACKB_BLOCKS = (KDIM / 32) * (NTOT / 32);   // 8192

// Scratch (allocation-free rule: __device__ globals)
__device__ __half g_A[(size_t)BATCH * KDIM];   // 32 MB: fp16 [x|h]
__device__ __half g_B[(size_t)NTOT * KDIM];    // 16 MB: fp16 W^T (K-major)
// 48 MB total: comfortably L2-resident.

// ---------------------------------------------------------------------------
// PTX helpers (base PTX only: cp.async / ldmatrix / mma.sync)
// ---------------------------------------------------------------------------
DINLINE uint32_t smem_u32(const void* p) {
    uint32_t a;
    asm("{ .reg .u64 t; cvta.to.shared.u64 t, %1; cvt.u32.u64 %0, t; }"
        : "=r"(a) : "l"(p));
    return a;
}

DINLINE void cp16(uint32_t dst, const void* src) {
    asm volatile("cp.async.cg.shared.global [%0], [%1], 16;"
                 :: "r"(dst), "l"(src) : "memory");
}
DINLINE void cp_commit() { asm volatile("cp.async.commit_group;" ::: "memory"); }
template <int N> DINLINE void cp_wait() {
    asm volatile("cp.async.wait_group %0;" :: "n"(N) : "memory");
}

DINLINE void l2_prefetch(const void* p) {
    asm volatile("prefetch.global.L2 [%0];" :: "l"(p));
}

// ldmatrix.x4 on fp16: native b16 use. Lane l of each 8x8 b16 matrix gets the
// 4B word [row=l/4][pair=l%4] -- exactly one fp16 mma fragment register.
DINLINE void ldsm4(uint32_t* r, uint32_t addr) {
    asm volatile("ldmatrix.sync.aligned.m8n8.x4.shared.b16 {%0,%1,%2,%3}, [%4];"
                 : "=r"(r[0]), "=r"(r[1]), "=r"(r[2]), "=r"(r[3]) : "r"(addr));
}

// fp16 m16n8k16: 2048 MACs/instr (2x tf32 m16n8k8), f32 accumulate.
DINLINE void mma_f16(float* d, const uint32_t* a, const uint32_t* b) {
    asm("mma.sync.aligned.m16n8k16.row.col.f32.f16.f16.f32 "
        "{%0,%1,%2,%3}, {%4,%5,%6,%7}, {%8,%9}, {%0,%1,%2,%3};"
        : "+f"(d[0]), "+f"(d[1]), "+f"(d[2]), "+f"(d[3])
        : "r"(a[0]), "r"(a[1]), "r"(a[2]), "r"(a[3]), "r"(b[0]), "r"(b[1]));
}

DINLINE uint32_t SWZ(uint32_t b) { return b ^ ((b >> 3) & 0x70); }

DINLINE float sigm(float x)  { return __fdividef(1.0f, 1.0f + __expf(-x)); }
DINLINE float tanhe(float x) { return 1.0f - __fdividef(2.0f, __expf(2.0f * x) + 1.0f); }

// ---------------------------------------------------------------------------
// Merged prep kernel: blocks [0, PACKA_BLOCKS) pack A=[x|h] -> fp16; the rest
// pack B=W^T (K-major) -> fp16. fp16 rna rounding has the SAME 10-bit mantissa
// as tf32 -> error profile identical to the measured 2.01e-4 config.
// ---------------------------------------------------------------------------
__global__ void pack_ab_kernel(const float* __restrict__ x,
                               const float* __restrict__ h,
                               const float* __restrict__ Wx,
                               const float* __restrict__ Wh) {
    const int tid = threadIdx.x;            // 256 threads
    if (blockIdx.x < PACKA_BLOCKS) {
        // ---- pack A: 8 floats -> 8 halves (16B store) ----
        size_t v = (size_t)blockIdx.x * 256 + tid;   // 8-half group index
        int m = (int)(v >> 8);              // 256 groups per 2048-wide row
        int q = (int)(v & 255);
        const float* src = (q < 128) ? (x + (size_t)m * HID + (size_t)q * 8)
                                     : (h + (size_t)m * HID + (size_t)(q - 128) * 8);
        float4 f0 = ((const float4*)src)[0];
        float4 f1 = ((const float4*)src)[1];
        __half2 r[4];
        r[0] = __floats2half2_rn(f0.x, f0.y);
        r[1] = __floats2half2_rn(f0.z, f0.w);
        r[2] = __floats2half2_rn(f1.x, f1.y);
        r[3] = __floats2half2_rn(f1.z, f1.w);
        *(uint4*)(g_A + v * 8) = *(const uint4*)r;
    } else {
        // ---- pack B: tf32... fp16-round + transpose W -> [N, K] ----
        __shared__ float tile[32][33];
        int bb = blockIdx.x - PACKA_BLOCKS;
        int k0 = (bb & 63) * 32;            // 64 k-blocks
        int n0 = (bb >> 6) * 32;            // 128 n-blocks
        int tx = tid & 31, ty = tid >> 5;   // (32, 8)
#pragma unroll
        for (int i = 0; i < 32; i += 8) {
            int k = k0 + ty + i;
            float v = (k < 1024) ? Wx[(size_t)k * NTOT + n0 + tx]
                                 : Wh[(size_t)(k - 1024) * NTOT + n0 + tx];
            tile[ty + i][tx] = v;
        }
        __syncthreads();
#pragma unroll
        for (int i = 0; i < 32; i += 8) {
            int n = n0 + ty + i;
            g_B[(size_t)n * KDIM + k0 + tx] = __float2half_rn(tile[tx][ty + i]);
        }
    }
}

// ---------------------------------------------------------------------------
// Fused GEMM + LSTM epilogue (cp.async + ldmatrix + mma.sync.f16)
// R4 mainloop (proven fastest): wait<2> -> sync -> compute -> sync -> refill.
// A k16 step = 32B/row = same footprint as the old tf32 k8 step -> fragment
// addressing is BIT-IDENTICAL to the validated tf32 code.
// ---------------------------------------------------------------------------
// Grid = (m fastest, nh slowest): all 64 CTAs of one nh0 column reuse the SAME
// B slice in L2 while A streams once.
//
// B smem row r (0..127) holds global N row:
//   n(r) = ((r>>4)&3)*1024 + nh0 + (r&15) + ((r>>6)&1)*16
// so each warp's 64 columns = {i,f,g,o} x 16 h-cols and each THREAD holds all
// four gate values for its (m, hcol) pairs -> register-only LSTM epilogue.
DINLINE void load_stage(uint32_t sbase, int s, int kc, int m0, int nh0, int tid) {
    const uint32_t sA = sbase + (uint32_t)s * STAGE_BYTES;
    const uint32_t sB = sA + STAGE_A;
    const __half* gA = g_A + (size_t)m0 * KDIM + (size_t)kc * KC;
    const __half* gB = g_B + (size_t)kc * KC;
#pragma unroll
    for (int i = 0; i < 8; i++) {          // A: 128 rows x 128B (64 fp16)
        int ch = tid + (i << 7);
        int r = ch >> 3, kb = ch & 7;
        uint32_t off = (uint32_t)(r * 128 + kb * 16);
        cp16(sA + SWZ(off), (const char*)(gA + (size_t)r * KDIM) + kb * 16);
    }
#pragma unroll
    for (int i = 0; i < 8; i++) {          // B: 128 gate-interleaved N rows x 128B
        int ch = tid + (i << 7);
        int r = ch >> 3, kb = ch & 7;
        int n = ((r >> 4) & 3) * 1024 + nh0 + (r & 15) + ((r >> 6) & 1) * 16;
        uint32_t off = (uint32_t)(r * 128 + kb * 16);
        cp16(sB + SWZ(off), (const char*)(gB + (size_t)n * KDIM) + kb * 16);
    }
}

__global__ void __launch_bounds__(128, 2)
lstm_gemm_kernel(const float* __restrict__ c_in, const float* __restrict__ bx,
                 float* __restrict__ h_out, float* __restrict__ c_out) {
    extern __shared__ __align__(16) char dynsmem[];
    __shared__ float s_bias[BN];

    const int tid = threadIdx.x;
    const int wid = tid >> 5;
    const int lid = tid & 31;
    const int m0  = blockIdx.x * BM;    // m fastest (proven best)
    const int nh0 = blockIdx.y * BNH;

    const int wm0 = (wid >> 1) * 64;   // warp M offset (2x2 warp grid, 64x64 tiles)
    const int wn0 = (wid & 1) * 64;    // warp N offset (smem B column space)

    uint32_t sbase = (smem_u32(dynsmem) + 1023u) & ~1023u;

    // bias cache, ordered identically to B smem columns
    {
        int r = tid;
        int n = ((r >> 4) & 3) * 1024 + nh0 + (r & 15) + ((r >> 6) & 1) * 16;
        s_bias[r] = bx[n];
    }

    // Warm L2 for the epilogue's c_in tile (one 128B line per thread).
    l2_prefetch(c_in + (size_t)(m0 + tid) * HID + nh0);

    // per-lane ldmatrix base offsets + constant swizzle mask (row&7)<<4.
    // fp16 A fragment {a0..a3} = {A[g][2t], A[g+8][2t], A[g][2t+8], A[g+8][2t+8]}
    //   -> matrices ROWS-first (same as tf32 A).
    // fp16 B fragment {b0,b1} = k-halves of one n8 -> matrices COLS-first.
    const uint32_t lrowA = (uint32_t)(((lid >> 3) & 1) * 8 + (lid & 7));
    const uint32_t lcolA = (uint32_t)(((lid >> 4) & 1) * 16);
    const uint32_t lrowB = (uint32_t)(((lid >> 4) & 1) * 8 + (lid & 7));
    const uint32_t lcolB = (uint32_t)(((lid >> 3) & 1) * 16);
    const uint32_t xm    = (uint32_t)((lid & 7) << 4);
    const uint32_t aOff = (uint32_t)(wm0 + lrowA) * 128u + lcolA;           // A tile
    const uint32_t bOff = STAGE_A + (uint32_t)(wn0 + lrowB) * 128u + lcolB; // B tile

    float acc[4][8][4];
#pragma unroll
    for (int i = 0; i < 4; i++)
#pragma unroll
        for (int j = 0; j < 8; j++)
#pragma unroll
            for (int r = 0; r < 4; r++) acc[i][j][r] = 0.0f;

    // prologue: fill all 3 stages (chunks 0..2)
    load_stage(sbase, 0, 0, m0, nh0, tid); cp_commit();
    load_stage(sbase, 1, 1, m0, nh0, tid); cp_commit();
    load_stage(sbase, 2, 2, m0, nh0, tid); cp_commit();

    int s = 0;
    for (int k = 0; k < KI; k++) {
        cp_wait<2>();        // chunk k complete (k+1, k+2 may pend)
        __syncthreads();     // chunk-k stores visible to all warps

        const uint32_t stA = sbase + (uint32_t)s * STAGE_BYTES + aOff;
        const uint32_t stB = sbase + (uint32_t)s * STAGE_BYTES + bOff;
#pragma unroll
        for (int ks = 0; ks < 4; ks++) {   // 4 k16 steps of 32B each
            uint32_t af[4][4], bf[4][4];
#pragma unroll
            for (int i = 0; i < 4; i++)
                ldsm4(af[i], (stA + (uint32_t)(i * 2048 + ks * 32)) ^ xm);
#pragma unroll
            for (int jp = 0; jp < 4; jp++)
                ldsm4(bf[jp], (stB + (uint32_t)(jp * 2048 + ks * 32)) ^ xm);
#pragma unroll
            for (int i = 0; i < 4; i++)
#pragma unroll
                for (int j = 0; j < 8; j++)
                    mma_f16(acc[i][j], af[i], &bf[j >> 1][(j & 1) * 2]);
        }

        __syncthreads();     // all warps done reading stage s
        if (k + 3 < KI) load_stage(sbase, s, k + 3, m0, nh0, tid);
        cp_commit();
        s++; if (s == NSTAGE) s = 0;
    }

    // ------------------------------------------------------------------
    // Register-only LSTM epilogue (C fragment layout identical to tf32).
    // acc[i][j][r]: row = m0+wm0+i*16 + lid/4 + (r>>1)*8
    //               smem col = wn0 + j*8 + 2*(lid&3) + (r&1)
    // smem col c -> gate=(c>>4)&3, hcol=((c>>6)&1)*16 + (c&15)
    // ------------------------------------------------------------------
    const int wHc = (wid & 1) * 16;
#pragma unroll
    for (int i = 0; i < 4; i++) {
#pragma unroll
        for (int rh = 0; rh < 2; rh++) {
            const int m = m0 + wm0 + i * 16 + (lid >> 2) + rh * 8;
            const float* crow = c_in + (size_t)m * HID + nh0;
            float* hrow  = h_out + (size_t)m * HID + nh0;
            float* corow = c_out + (size_t)m * HID + nh0;
#pragma unroll
            for (int hb = 0; hb < 2; hb++) {
#pragma unroll
                for (int cc = 0; cc < 2; cc++) {
                    const int hc   = wHc + hb * 8 + (lid & 3) * 2 + cc;
                    const int colb = wn0 + hb * 8 + (lid & 3) * 2 + cc; // gate 0 col
                    const int rr   = rh * 2 + cc;
                    float zi = acc[i][0 + hb][rr] + s_bias[colb];
                    float zf = acc[i][2 + hb][rr] + s_bias[colb + 16];
                    float zg = acc[i][4 + hb][rr] + s_bias[colb + 32];
                    float zo = acc[i][6 + hb][rr] + s_bias[colb + 48];
                    float iv = sigm(zi), fv = sigm(zf);
                    float gv = tanhe(zg), ov = sigm(zo);
                    float cn = fv * crow[hc] + iv * gv;
                    corow[hc] = cn;
                    hrow[hc]  = ov * tanhe(cn);
                }
            }
        }
    }
}

// ---------------------------------------------------------------------------
// Launcher
// ---------------------------------------------------------------------------
extern "C" void kernel_launch(void* const* d_in, const int* in_sizes, int n_in,
                              void* d_out, int out_size) {
    (void)in_sizes; (void)n_in; (void)out_size;
    const float* x  = (const float*)d_in[0];
    const float* h  = (const float*)d_in[1];
    const float* c  = (const float*)d_in[2];
    const float* Wx = (const float*)d_in[3];
    const float* bx = (const float*)d_in[4];
    const float* Wh = (const float*)d_in[5];
    float* out   = (float*)d_out;
    float* h_out = out;
    float* c_out = out + (size_t)BATCH * HID;

    cudaFuncSetAttribute(lstm_gemm_kernel,
                         cudaFuncAttributeMaxDynamicSharedMemorySize, DYN_SMEM);

    // Merged prep: fp16-round + pack A=[x|h] and B=W^T in ONE launch
    pack_ab_kernel<<<PACKA_BLOCKS + PACKB_BLOCKS, 256>>>(x, h, Wx, Wh);

    // Fused GEMM + LSTM epilogue (m0 fastest -> co-resident CTAs share B slice)
    lstm_gemm_kernel<<<dim3(BATCH / BM, HID / BNH), 128, DYN_SMEM>>>(
        c, bx, h_out, c_out);
}